// round 2
// baseline (speedup 1.0000x reference)
#include <cuda_runtime.h>

#define SA   65536   // S*A = S*O = 512*128
#define DK   64
#define DIM  256
#define NH   8
#define EMB  512

// Scratch (static device globals: allocation-guard safe)
__device__ float g_K[(size_t)NH * SA * DK];
__device__ float g_Q[(size_t)NH * SA * DK];
__device__ float g_V[(size_t)NH * SA * DK];
__device__ float g_Hd[(size_t)SA * EMB];

// ---------------------------------------------------------------------------
// K1: per-head projections  Y[h] = X @ W[h]   (65536x256 @ 256x64)
// grid (512 row-tiles, 8 heads, 3 matrices), 256 threads
// ---------------------------------------------------------------------------
__global__ __launch_bounds__(256) void proj_kernel(
    const float* __restrict__ hIn, const float* __restrict__ hOppIn,
    const float* __restrict__ Wq, const float* __restrict__ Wk,
    const float* __restrict__ Wv)
{
    __shared__ float sAt[32 * 128];  // transposed + swizzled A chunk
    __shared__ float sW [32 * 64];   // W chunk (row-major)

    const float* X; const float* W; float* Y;
    if (blockIdx.z == 0)      { X = hIn;    W = Wk; Y = g_K; }
    else if (blockIdx.z == 1) { X = hOppIn; W = Wq; Y = g_Q; }
    else                      { X = hOppIn; W = Wv; Y = g_V; }
    int head = blockIdx.y;
    W += head * DIM * DK;
    Y += (size_t)head * SA * DK;

    int row0 = blockIdx.x * 128;
    int tid = threadIdx.x;
    int tx = tid & 15, ty = tid >> 4;

    float acc[8][4];
    #pragma unroll
    for (int i = 0; i < 8; i++)
        #pragma unroll
        for (int j = 0; j < 4; j++) acc[i][j] = 0.f;

    for (int k0 = 0; k0 < DIM; k0 += 32) {
        __syncthreads();
        // A chunk: 128 rows x 32 k  -> sAt[kk][col], col = a ^ ((kk>>2)<<2)
        #pragma unroll
        for (int l = 0; l < 4; l++) {
            int idx = l * 256 + tid;
            int a  = idx >> 3;
            int kv = idx & 7;
            float4 v = *(const float4*)&X[(size_t)(row0 + a) * DIM + k0 + kv * 4];
            int col = a ^ (kv << 2);
            sAt[(kv * 4 + 0) * 128 + col] = v.x;
            sAt[(kv * 4 + 1) * 128 + col] = v.y;
            sAt[(kv * 4 + 2) * 128 + col] = v.z;
            sAt[(kv * 4 + 3) * 128 + col] = v.w;
        }
        // W chunk: 32 x 64
        #pragma unroll
        for (int l = 0; l < 2; l++) {
            int idx = l * 256 + tid;
            int kk = idx >> 4;
            int wv = idx & 15;
            *(float4*)&sW[kk * 64 + wv * 4] =
                *(const float4*)&W[(k0 + kk) * DK + wv * 4];
        }
        __syncthreads();
        #pragma unroll 8
        for (int kk = 0; kk < 32; kk++) {
            int sw = (kk >> 2) << 2;
            float4 a0 = *(const float4*)&sAt[kk * 128 + ((ty * 4) ^ sw)];
            float4 a1 = *(const float4*)&sAt[kk * 128 + (((ty * 4) ^ sw) + 64)];
            float4 b  = *(const float4*)&sW [kk * 64 + tx * 4];
            float av[8] = {a0.x, a0.y, a0.z, a0.w, a1.x, a1.y, a1.z, a1.w};
            float bv[4] = {b.x, b.y, b.z, b.w};
            #pragma unroll
            for (int i = 0; i < 8; i++)
                #pragma unroll
                for (int j = 0; j < 4; j++)
                    acc[i][j] = fmaf(av[i], bv[j], acc[i][j]);
        }
    }
    #pragma unroll
    for (int i = 0; i < 8; i++) {
        int r = (i < 4) ? (ty * 4 + i) : (64 + ty * 4 + (i - 4));
        float4 v = make_float4(acc[i][0], acc[i][1], acc[i][2], acc[i][3]);
        *(float4*)&Y[(size_t)(row0 + r) * DK + tx * 4] = v;
    }
}

// ---------------------------------------------------------------------------
// K2: per-tile attention.  tile s: head = s>>6, b = s&63.
//   Kv/Qv/Vv = per-head rows [b*1024, +1024) reinterpreted as (128 x 512).
//   C = Kv @ Qv^T * 0.125 ; P = softmax_row(C) ; Hd = P @ Vv -> g_Hd
// 512 blocks, 256 threads, dynamic smem
// ---------------------------------------------------------------------------
#define ATTN_SMEM ((128 * 129 + 128 * 68) * 4)

__global__ __launch_bounds__(256) void attn_kernel()
{
    extern __shared__ float sm[];
    float* sKt = sm;                  // 64*128 (phase 1)
    float* sQt = sm + 64 * 128;       // 64*128 (phase 1)
    float* sP  = sm;                  // 128*129 (phases 2-3, reuses phase-1 space)
    float* sV  = sm + 128 * 129;      // 128*68  (phase 3)

    int s = blockIdx.x;
    int head = s >> 6;
    int b = s & 63;
    size_t base = (size_t)head * SA * DK + (size_t)b * 1024 * DK;
    const float* Kv = g_K + base;     // (128 x 512) row-major view
    const float* Qv = g_Q + base;
    const float* Vv = g_V + base;

    int tid = threadIdx.x;
    int tx = tid & 15, ty = tid >> 4;

    float acc[8][8];
    #pragma unroll
    for (int i = 0; i < 8; i++)
        #pragma unroll
        for (int j = 0; j < 8; j++) acc[i][j] = 0.f;

    // ---- phase 1: C = Kv @ Qv^T -----------------------------------------
    for (int k0 = 0; k0 < 512; k0 += 64) {
        __syncthreads();
        #pragma unroll
        for (int l = 0; l < 8; l++) {
            int idx = l * 256 + tid;
            int a  = idx >> 4;
            int kv = idx & 15;
            int col = a ^ ((kv & 7) << 2);
            float4 vk = *(const float4*)&Kv[(size_t)a * 512 + k0 + kv * 4];
            sKt[(kv * 4 + 0) * 128 + col] = vk.x;
            sKt[(kv * 4 + 1) * 128 + col] = vk.y;
            sKt[(kv * 4 + 2) * 128 + col] = vk.z;
            sKt[(kv * 4 + 3) * 128 + col] = vk.w;
            float4 vq = *(const float4*)&Qv[(size_t)a * 512 + k0 + kv * 4];
            sQt[(kv * 4 + 0) * 128 + col] = vq.x;
            sQt[(kv * 4 + 1) * 128 + col] = vq.y;
            sQt[(kv * 4 + 2) * 128 + col] = vq.z;
            sQt[(kv * 4 + 3) * 128 + col] = vq.w;
        }
        __syncthreads();
        #pragma unroll 8
        for (int kk = 0; kk < 64; kk++) {
            int sw = ((kk >> 2) & 7) << 2;
            float4 a0 = *(const float4*)&sKt[kk * 128 + ((ty * 4) ^ sw)];
            float4 a1 = *(const float4*)&sKt[kk * 128 + (((ty * 4) ^ sw) + 64)];
            float4 b0 = *(const float4*)&sQt[kk * 128 + ((tx * 4) ^ sw)];
            float4 b1 = *(const float4*)&sQt[kk * 128 + (((tx * 4) ^ sw) + 64)];
            float av[8] = {a0.x, a0.y, a0.z, a0.w, a1.x, a1.y, a1.z, a1.w};
            float bv[8] = {b0.x, b0.y, b0.z, b0.w, b1.x, b1.y, b1.z, b1.w};
            #pragma unroll
            for (int i = 0; i < 8; i++)
                #pragma unroll
                for (int j = 0; j < 8; j++)
                    acc[i][j] = fmaf(av[i], bv[j], acc[i][j]);
        }
    }

    // ---- phase 2: softmax rows (reduce across the 16 tx lanes) ----------
    const float norm = 0.125f;
    #pragma unroll
    for (int i = 0; i < 8; i++) {
        float m = -1e30f;
        #pragma unroll
        for (int j = 0; j < 8; j++) { acc[i][j] *= norm; m = fmaxf(m, acc[i][j]); }
        #pragma unroll
        for (int off = 8; off > 0; off >>= 1)
            m = fmaxf(m, __shfl_xor_sync(0xffffffffu, m, off, 16));
        float ssum = 0.f;
        #pragma unroll
        for (int j = 0; j < 8; j++) { acc[i][j] = __expf(acc[i][j] - m); ssum += acc[i][j]; }
        #pragma unroll
        for (int off = 8; off > 0; off >>= 1)
            ssum += __shfl_xor_sync(0xffffffffu, ssum, off, 16);
        float inv = 1.f / ssum;
        #pragma unroll
        for (int j = 0; j < 8; j++) acc[i][j] *= inv;
    }
    __syncthreads();   // phase-1 buffers fully read; safe to overwrite with P
    #pragma unroll
    for (int i = 0; i < 8; i++) {
        int r = (i < 4) ? (ty * 4 + i) : (64 + ty * 4 + (i - 4));
        #pragma unroll
        for (int j = 0; j < 8; j++) {
            int o = (j < 4) ? (tx * 4 + j) : (64 + tx * 4 + (j - 4));
            sP[r * 129 + o] = acc[i][j];
        }
    }

    // ---- phase 3: Hd = P @ Vv, streamed over 8 column chunks ------------
    // Precompute the 8 P-row base pointers once (they don't depend on cc/o).
    const float* pRow[8];
    #pragma unroll
    for (int i = 0; i < 8; i++) {
        int r = (i < 4) ? (ty * 4 + i) : (64 + ty * 4 + (i - 4));
        pRow[i] = &sP[r * 129];
    }

    #pragma unroll 1
    for (int cc = 0; cc < 8; cc++) {
        __syncthreads();   // also covers sP visibility on first iteration
        #pragma unroll
        for (int l = 0; l < 8; l++) {
            int idx = l * 256 + tid;
            int o  = idx >> 4;
            int cv = idx & 15;
            *(float4*)&sV[o * 68 + cv * 4] =
                *(const float4*)&Vv[(size_t)o * 512 + cc * 64 + cv * 4];
        }
        __syncthreads();
        float acc2[8][4];
        #pragma unroll
        for (int i = 0; i < 8; i++)
            #pragma unroll
            for (int j = 0; j < 4; j++) acc2[i][j] = 0.f;
        #pragma unroll 8
        for (int o = 0; o < 128; o++) {
            float4 bvec = *(const float4*)&sV[o * 68 + tx * 4];
            float bv[4] = {bvec.x, bvec.y, bvec.z, bvec.w};
            float pa[8];
            #pragma unroll
            for (int i = 0; i < 8; i++) pa[i] = pRow[i][o];
            #pragma unroll
            for (int i = 0; i < 8; i++)
                #pragma unroll
                for (int j = 0; j < 4; j++)
                    acc2[i][j] = fmaf(pa[i], bv[j], acc2[i][j]);
        }
        #pragma unroll
        for (int i = 0; i < 8; i++) {
            int r = (i < 4) ? (ty * 4 + i) : (64 + ty * 4 + (i - 4));
            *(float4*)&g_Hd[((size_t)s * 128 + r) * 512 + cc * 64 + tx * 4] =
                make_float4(acc2[i][0], acc2[i][1], acc2[i][2], acc2[i][3]);
        }
    }
}

// ---------------------------------------------------------------------------
// K3: out = g_Hd (65536x512) @ Wout (512x512)
// grid (512 row-tiles, 4 col-tiles), 256 threads, 128x128 tile, 8x8/thread
// ---------------------------------------------------------------------------
__global__ __launch_bounds__(256) void out_kernel(
    const float* __restrict__ Wout, float* __restrict__ out)
{
    __shared__ float sAt[32 * 128];
    __shared__ float sB [32 * 132];

    int row0 = blockIdx.x * 128;
    int e0   = blockIdx.y * 128;
    int tid = threadIdx.x;
    int tx = tid & 15, ty = tid >> 4;

    float acc[8][8];
    #pragma unroll
    for (int i = 0; i < 8; i++)
        #pragma unroll
        for (int j = 0; j < 8; j++) acc[i][j] = 0.f;

    for (int k0 = 0; k0 < 512; k0 += 32) {
        __syncthreads();
        #pragma unroll
        for (int l = 0; l < 4; l++) {
            int idx = l * 256 + tid;
            int a  = idx >> 3;
            int kv = idx & 7;
            float4 v = *(const float4*)&g_Hd[(size_t)(row0 + a) * 512 + k0 + kv * 4];
            int col = a ^ (kv << 2);
            sAt[(kv * 4 + 0) * 128 + col] = v.x;
            sAt[(kv * 4 + 1) * 128 + col] = v.y;
            sAt[(kv * 4 + 2) * 128 + col] = v.z;
            sAt[(kv * 4 + 3) * 128 + col] = v.w;
        }
        #pragma unroll
        for (int l = 0; l < 4; l++) {
            int idx = l * 256 + tid;
            int kk = idx >> 5;
            int ev = idx & 31;
            *(float4*)&sB[kk * 132 + ev * 4] =
                *(const float4*)&Wout[(size_t)(k0 + kk) * 512 + e0 + ev * 4];
        }
        __syncthreads();
        #pragma unroll 8
        for (int kk = 0; kk < 32; kk++) {
            int sw = (kk >> 2) << 2;
            float4 a0 = *(const float4*)&sAt[kk * 128 + ((ty * 4) ^ sw)];
            float4 a1 = *(const float4*)&sAt[kk * 128 + (((ty * 4) ^ sw) + 64)];
            float4 b0 = *(const float4*)&sB[kk * 132 + tx * 4];
            float4 b1 = *(const float4*)&sB[kk * 132 + tx * 4 + 64];
            float av[8] = {a0.x, a0.y, a0.z, a0.w, a1.x, a1.y, a1.z, a1.w};
            float bv[8] = {b0.x, b0.y, b0.z, b0.w, b1.x, b1.y, b1.z, b1.w};
            #pragma unroll
            for (int i = 0; i < 8; i++)
                #pragma unroll
                for (int j = 0; j < 8; j++)
                    acc[i][j] = fmaf(av[i], bv[j], acc[i][j]);
        }
    }
    #pragma unroll
    for (int i = 0; i < 8; i++) {
        int r = (i < 4) ? (ty * 4 + i) : (64 + ty * 4 + (i - 4));
        *(float4*)&out[(size_t)(row0 + r) * 512 + e0 + tx * 4] =
            make_float4(acc[i][0], acc[i][1], acc[i][2], acc[i][3]);
        *(float4*)&out[(size_t)(row0 + r) * 512 + e0 + 64 + tx * 4] =
            make_float4(acc[i][4], acc[i][5], acc[i][6], acc[i][7]);
    }
}

// ---------------------------------------------------------------------------
extern "C" void kernel_launch(void* const* d_in, const int* in_sizes, int n_in,
                              void* d_out, int out_size)
{
    (void)in_sizes; (void)n_in; (void)out_size;
    const float* h    = (const float*)d_in[0];
    const float* hOpp = (const float*)d_in[1];
    const float* Wq   = (const float*)d_in[2];
    const float* Wk   = (const float*)d_in[3];
    const float* Wv   = (const float*)d_in[4];
    const float* Wout = (const float*)d_in[5];
    float* out = (float*)d_out;

    // Idempotent, host-side, deterministic; not a stream op (capture-safe).
    cudaFuncSetAttribute(attn_kernel,
                         cudaFuncAttributeMaxDynamicSharedMemorySize, ATTN_SMEM);

    proj_kernel<<<dim3(512, 8, 3), 256>>>(h, hOpp, Wq, Wk, Wv);
    attn_kernel<<<512, 256, ATTN_SMEM>>>();
    out_kernel<<<dim3(512, 4), 256>>>(Wout, out);
}

// round 6
// speedup vs baseline: 1.8454x; 1.8454x over previous
#include <cuda_runtime.h>
#include <cuda_bf16.h>
#include <cstdint>

#define SA 65536

// ---------------- scratch (static device globals) --------------------------
__device__ float g_K [(size_t)SA * 512];   // layout [n][h*64+k]
__device__ float g_Q [(size_t)SA * 512];
__device__ float g_V [(size_t)SA * 512];

__device__ __nv_bfloat16 g_hH[(size_t)SA * 256], g_hL[(size_t)SA * 256];
__device__ __nv_bfloat16 g_oH[(size_t)SA * 256], g_oL[(size_t)SA * 256];
__device__ __nv_bfloat16 g_WtH[3][512 * 256], g_WtL[3][512 * 256]; // 0=K,1=Q,2=V : [n][d]
__device__ __nv_bfloat16 g_WoH[512 * 512],  g_WoL[512 * 512];      // [e][n]
__device__ __nv_bfloat16 g_HdH[(size_t)SA * 512], g_HdL[(size_t)SA * 512];

// ---------------- helpers ---------------------------------------------------
__device__ __forceinline__ void split1(float x, __nv_bfloat16& hi, __nv_bfloat16& lo) {
    hi = __float2bfloat16(x);
    lo = __float2bfloat16(x - __bfloat162float(hi));
}
__device__ __forceinline__ uint32_t s2u(const void* p) {
    uint32_t a;
    asm("{ .reg .u64 t; cvta.to.shared.u64 t, %1; cvt.u32.u64 %0, t; }" : "=r"(a) : "l"(p));
    return a;
}
__device__ __forceinline__ void ldsm4(uint32_t addr, uint32_t& r0, uint32_t& r1,
                                      uint32_t& r2, uint32_t& r3) {
    asm volatile("ldmatrix.sync.aligned.m8n8.x4.shared.b16 {%0,%1,%2,%3}, [%4];"
                 : "=r"(r0), "=r"(r1), "=r"(r2), "=r"(r3) : "r"(addr));
}
__device__ __forceinline__ void ldsm2(uint32_t addr, uint32_t& r0, uint32_t& r1) {
    asm volatile("ldmatrix.sync.aligned.m8n8.x2.shared.b16 {%0,%1}, [%2];"
                 : "=r"(r0), "=r"(r1) : "r"(addr));
}
__device__ __forceinline__ void mma16816(float& c0, float& c1, float& c2, float& c3,
                                         uint32_t a0, uint32_t a1, uint32_t a2, uint32_t a3,
                                         uint32_t b0, uint32_t b1) {
    asm volatile(
        "mma.sync.aligned.m16n8k16.row.col.f32.bf16.bf16.f32 "
        "{%0,%1,%2,%3}, {%4,%5,%6,%7}, {%8,%9}, {%0,%1,%2,%3};"
        : "+f"(c0), "+f"(c1), "+f"(c2), "+f"(c3)
        : "r"(a0), "r"(a1), "r"(a2), "r"(a3), "r"(b0), "r"(b1));
}
__device__ __forceinline__ void cp16(uint32_t dst, const void* src) {
    asm volatile("cp.async.cg.shared.global [%0], [%1], 16;"
                 :: "r"(dst), "l"(__cvta_generic_to_global(src)));
}
__device__ __forceinline__ void cp_commit() {
    asm volatile("cp.async.commit_group;" ::: "memory");
}
template <int N>
__device__ __forceinline__ void cp_wait() {
    asm volatile("cp.async.wait_group %0;" :: "n"(N) : "memory");
}

// ---------------- split kernels --------------------------------------------
__global__ __launch_bounds__(256) void split_x(const float* __restrict__ h,
                                               const float* __restrict__ ho) {
    size_t i = ((size_t)blockIdx.x * 256 + threadIdx.x) * 4;
    const float* src = blockIdx.y ? ho : h;
    __nv_bfloat16* dh = blockIdx.y ? g_oH : g_hH;
    __nv_bfloat16* dl = blockIdx.y ? g_oL : g_hL;
    float4 v = *(const float4*)(src + i);
    __nv_bfloat16 a0,a1,a2,a3,b0,b1,b2,b3;
    split1(v.x,a0,b0); split1(v.y,a1,b1); split1(v.z,a2,b2); split1(v.w,a3,b3);
    __nv_bfloat162 t;
    t.x=a0; t.y=a1; *(__nv_bfloat162*)(dh+i)   = t;
    t.x=a2; t.y=a3; *(__nv_bfloat162*)(dh+i+2) = t;
    t.x=b0; t.y=b1; *(__nv_bfloat162*)(dl+i)   = t;
    t.x=b2; t.y=b3; *(__nv_bfloat162*)(dl+i+2) = t;
}

__global__ void wsplit(const float* __restrict__ Wq, const float* __restrict__ Wk,
                       const float* __restrict__ Wv) {
    int n = blockIdx.x;          // 0..511  (= h*64+k)
    int d = threadIdx.x;         // 0..255
    int m = blockIdx.y;          // 0=K,1=Q,2=V
    const float* W = (m == 0) ? Wk : ((m == 1) ? Wq : Wv);
    float w = W[(n >> 6) * 16384 + d * 64 + (n & 63)];
    __nv_bfloat16 hi, lo; split1(w, hi, lo);
    g_WtH[m][n * 256 + d] = hi;
    g_WtL[m][n * 256 + d] = lo;
}

__global__ void wosplit(const float* __restrict__ Wo) {
    int e = blockIdx.x;          // 0..511 output col
    int n = threadIdx.x;         // 0..511 input (h*64+k)
    float w = Wo[n * 512 + e];
    __nv_bfloat16 hi, lo; split1(w, hi, lo);
    g_WoH[e * 512 + n] = hi;
    g_WoL[e * 512 + n] = lo;
}

// ---------------- HMMA GEMM: C(65536x512) = (Ah+Al) @ (Bh+Bl)^T -------------
// B rows = output cols (K-major).  Split: AhBh + AhBl + AlBh.
// CTA tile 128x128, 8 warps (2x4), warp 64x32, K chunk 32, cp.async 2-stage.
#define RS      80          // smem row stride bytes (40 bf16)
#define MATB    10240       // 128 rows * 80B
#define STAGE   40960       // 4 matrices
#define GEMM_SMEM (2 * STAGE)

__global__ __launch_bounds__(256, 2) void gemm_hmma(int modeSel, float* __restrict__ outp)
{
    extern __shared__ char smc[];
    int mode = (modeSel < 0) ? (int)blockIdx.z : modeSel;

    const __nv_bfloat16 *Ah, *Al, *Bh, *Bl; float* C; int kdim;
    if      (mode == 0) { Ah=g_hH;  Al=g_hL;  Bh=g_WtH[0]; Bl=g_WtL[0]; C=g_K;  kdim=256; }
    else if (mode == 1) { Ah=g_oH;  Al=g_oL;  Bh=g_WtH[1]; Bl=g_WtL[1]; C=g_Q;  kdim=256; }
    else if (mode == 2) { Ah=g_oH;  Al=g_oL;  Bh=g_WtH[2]; Bl=g_WtL[2]; C=g_V;  kdim=256; }
    else                { Ah=g_HdH; Al=g_HdL; Bh=g_WoH;    Bl=g_WoL;    C=outp; kdim=512; }

    const int tid  = threadIdx.x;
    const int lane = tid & 31;
    const int wid  = tid >> 5;
    const int wm   = (wid >> 2) * 64;     // warp m offset in tile
    const int wn   = (wid & 3) * 32;      // warp n offset in tile
    const int row0 = blockIdx.x * 128;
    const int n0   = blockIdx.y * 128;
    const int nch  = kdim >> 5;

    const uint32_t sb = s2u(smc);
    const __nv_bfloat16* srcs[4] = { Ah + (size_t)row0 * kdim, Al + (size_t)row0 * kdim,
                                     Bh + (size_t)n0   * kdim, Bl + (size_t)n0   * kdim };

    // loader: 2048 x 16B granules per stage, 8 per thread
    auto load_chunk = [&](int i, int st) {
        uint32_t sbase = sb + st * STAGE;
        size_t k0 = (size_t)i * 32;
        #pragma unroll
        for (int it = 0; it < 8; it++) {
            int g   = it * 256 + tid;
            int mat = g >> 9;
            int rem = g & 511;
            int r   = rem >> 2, j = rem & 3;
            cp16(sbase + mat * MATB + r * RS + j * 16,
                 srcs[mat] + (size_t)r * kdim + k0 + j * 8);
        }
    };

    float c[4][4][4];
    #pragma unroll
    for (int mt = 0; mt < 4; mt++)
        #pragma unroll
        for (int nt = 0; nt < 4; nt++)
            #pragma unroll
            for (int q = 0; q < 4; q++) c[mt][nt][q] = 0.f;

    load_chunk(0, 0); cp_commit();

    // per-thread ldmatrix address components
    const int a_row = lane & 15, a_hk = (lane >> 4) * 16;     // x4: 16B col group
    const int b_row = lane & 7,  b_hk = ((lane >> 3) & 1) * 16;

    for (int i = 0; i < nch; i++) {
        if (i + 1 < nch) { load_chunk(i + 1, (i + 1) & 1); cp_commit(); cp_wait<1>(); }
        else             { cp_wait<0>(); }
        __syncthreads();

        uint32_t stb = sb + (i & 1) * STAGE;
        #pragma unroll
        for (int ks = 0; ks < 2; ks++) {
            uint32_t a_h[4][4];
            uint32_t aAddrH = stb + (wm + a_row) * RS + ks * 32 + a_hk;
            uint32_t aAddrL = aAddrH + MATB;
            uint32_t bAddrH = stb + 2 * MATB + (wn + b_row) * RS + ks * 32 + b_hk;
            uint32_t bAddrL = bAddrH + MATB;

            #pragma unroll
            for (int mt = 0; mt < 4; mt++)
                ldsm4(aAddrH + mt * 16 * RS, a_h[mt][0], a_h[mt][1], a_h[mt][2], a_h[mt][3]);
            // pass 1: Ah * Bh
            #pragma unroll
            for (int nt = 0; nt < 4; nt++) {
                uint32_t b0, b1;
                ldsm2(bAddrH + nt * 8 * RS, b0, b1);
                #pragma unroll
                for (int mt = 0; mt < 4; mt++)
                    mma16816(c[mt][nt][0], c[mt][nt][1], c[mt][nt][2], c[mt][nt][3],
                             a_h[mt][0], a_h[mt][1], a_h[mt][2], a_h[mt][3], b0, b1);
            }
            // pass 2: Ah * Bl
            #pragma unroll
            for (int nt = 0; nt < 4; nt++) {
                uint32_t b0, b1;
                ldsm2(bAddrL + nt * 8 * RS, b0, b1);
                #pragma unroll
                for (int mt = 0; mt < 4; mt++)
                    mma16816(c[mt][nt][0], c[mt][nt][1], c[mt][nt][2], c[mt][nt][3],
                             a_h[mt][0], a_h[mt][1], a_h[mt][2], a_h[mt][3], b0, b1);
            }
            // pass 3: Al * Bh  (reuse a_h regs)
            #pragma unroll
            for (int mt = 0; mt < 4; mt++)
                ldsm4(aAddrL + mt * 16 * RS, a_h[mt][0], a_h[mt][1], a_h[mt][2], a_h[mt][3]);
            #pragma unroll
            for (int nt = 0; nt < 4; nt++) {
                uint32_t b0, b1;
                ldsm2(bAddrH + nt * 8 * RS, b0, b1);
                #pragma unroll
                for (int mt = 0; mt < 4; mt++)
                    mma16816(c[mt][nt][0], c[mt][nt][1], c[mt][nt][2], c[mt][nt][3],
                             a_h[mt][0], a_h[mt][1], a_h[mt][2], a_h[mt][3], b0, b1);
            }
        }
        __syncthreads();
    }

    // epilogue
    #pragma unroll
    for (int mt = 0; mt < 4; mt++) {
        int rg = row0 + wm + mt * 16 + (lane >> 2);
        #pragma unroll
        for (int nt = 0; nt < 4; nt++) {
            int cg = n0 + wn + nt * 8 + 2 * (lane & 3);
            float2 v0 = make_float2(c[mt][nt][0], c[mt][nt][1]);
            float2 v1 = make_float2(c[mt][nt][2], c[mt][nt][3]);
            *(float2*)(C + (size_t)rg * 512 + cg)       = v0;
            *(float2*)(C + (size_t)(rg + 8) * 512 + cg) = v1;
        }
    }
}

// ---------------- attention (fp32, [n][h*64+k] layout) ----------------------
// Epilogue writes bf16 split (HdH/HdL) directly — no separate split_hd pass.
#define ATTN_SMEM ((128 * 129 + 128 * 68) * 4)

__global__ __launch_bounds__(256) void attn_kernel()
{
    extern __shared__ float smf[];
    float* sKt = smf;
    float* sQt = smf + 64 * 128;
    float* sP  = smf;
    float* sV  = smf + 128 * 129;

    int s = blockIdx.x;
    int head = s >> 6;
    int b = s & 63;
    const float* Kbase = g_K + (size_t)b * 1024 * 512 + head * 64;
    const float* Qbase = g_Q + (size_t)b * 1024 * 512 + head * 64;
    const float* Vbase = g_V + (size_t)b * 1024 * 512 + head * 64;

    int tid = threadIdx.x;
    int tx = tid & 15, ty = tid >> 4;

    float acc[8][8];
    #pragma unroll
    for (int i = 0; i < 8; i++)
        #pragma unroll
        for (int j = 0; j < 8; j++) acc[i][j] = 0.f;

    for (int k0 = 0; k0 < 512; k0 += 64) {
        int kc = k0 >> 6;
        __syncthreads();
        #pragma unroll
        for (int l = 0; l < 8; l++) {
            int idx = l * 256 + tid;
            int a  = idx >> 4;
            int kv = idx & 15;
            int col = a ^ ((kv & 7) << 2);
            float4 vk = *(const float4*)&Kbase[(size_t)(a * 8 + kc) * 512 + kv * 4];
            sKt[(kv * 4 + 0) * 128 + col] = vk.x;
            sKt[(kv * 4 + 1) * 128 + col] = vk.y;
            sKt[(kv * 4 + 2) * 128 + col] = vk.z;
            sKt[(kv * 4 + 3) * 128 + col] = vk.w;
            float4 vq = *(const float4*)&Qbase[(size_t)(a * 8 + kc) * 512 + kv * 4];
            sQt[(kv * 4 + 0) * 128 + col] = vq.x;
            sQt[(kv * 4 + 1) * 128 + col] = vq.y;
            sQt[(kv * 4 + 2) * 128 + col] = vq.z;
            sQt[(kv * 4 + 3) * 128 + col] = vq.w;
        }
        __syncthreads();
        #pragma unroll 8
        for (int kk = 0; kk < 64; kk++) {
            int sw = ((kk >> 2) & 7) << 2;
            float4 a0 = *(const float4*)&sKt[kk * 128 + ((ty * 4) ^ sw)];
            float4 a1 = *(const float4*)&sKt[kk * 128 + (((ty * 4) ^ sw) + 64)];
            float4 b0 = *(const float4*)&sQt[kk * 128 + ((tx * 4) ^ sw)];
            float4 b1 = *(const float4*)&sQt[kk * 128 + (((tx * 4) ^ sw) + 64)];
            float av[8] = {a0.x, a0.y, a0.z, a0.w, a1.x, a1.y, a1.z, a1.w};
            float bv[8] = {b0.x, b0.y, b0.z, b0.w, b1.x, b1.y, b1.z, b1.w};
            #pragma unroll
            for (int i = 0; i < 8; i++)
                #pragma unroll
                for (int j = 0; j < 8; j++)
                    acc[i][j] = fmaf(av[i], bv[j], acc[i][j]);
        }
    }

    const float norm = 0.125f;
    #pragma unroll
    for (int i = 0; i < 8; i++) {
        float m = -1e30f;
        #pragma unroll
        for (int j = 0; j < 8; j++) { acc[i][j] *= norm; m = fmaxf(m, acc[i][j]); }
        #pragma unroll
        for (int off = 8; off > 0; off >>= 1)
            m = fmaxf(m, __shfl_xor_sync(0xffffffffu, m, off, 16));
        float ssum = 0.f;
        #pragma unroll
        for (int j = 0; j < 8; j++) { acc[i][j] = __expf(acc[i][j] - m); ssum += acc[i][j]; }
        #pragma unroll
        for (int off = 8; off > 0; off >>= 1)
            ssum += __shfl_xor_sync(0xffffffffu, ssum, off, 16);
        float inv = 1.f / ssum;
        #pragma unroll
        for (int j = 0; j < 8; j++) acc[i][j] *= inv;
    }
    __syncthreads();
    #pragma unroll
    for (int i = 0; i < 8; i++) {
        int r = (i < 4) ? (ty * 4 + i) : (64 + ty * 4 + (i - 4));
        #pragma unroll
        for (int j = 0; j < 8; j++) {
            int o = (j < 4) ? (tx * 4 + j) : (64 + tx * 4 + (j - 4));
            sP[r * 129 + o] = acc[i][j];
        }
    }

    const float* pRow[8];
    #pragma unroll
    for (int i = 0; i < 8; i++) {
        int r = (i < 4) ? (ty * 4 + i) : (64 + ty * 4 + (i - 4));
        pRow[i] = &sP[r * 129];
    }

    #pragma unroll 1
    for (int cc = 0; cc < 8; cc++) {
        __syncthreads();
        #pragma unroll
        for (int l = 0; l < 8; l++) {
            int idx = l * 256 + tid;
            int o  = idx >> 4;
            int cv = idx & 15;
            *(float4*)&sV[o * 68 + cv * 4] =
                *(const float4*)&Vbase[(size_t)(o * 8 + cc) * 512 + cv * 4];
        }
        __syncthreads();
        float acc2[8][4];
        #pragma unroll
        for (int i = 0; i < 8; i++)
            #pragma unroll
            for (int j = 0; j < 4; j++) acc2[i][j] = 0.f;
        #pragma unroll 8
        for (int o = 0; o < 128; o++) {
            float4 bvec = *(const float4*)&sV[o * 68 + tx * 4];
            float bv[4] = {bvec.x, bvec.y, bvec.z, bvec.w};
            float pa[8];
            #pragma unroll
            for (int i = 0; i < 8; i++) pa[i] = pRow[i][o];
            #pragma unroll
            for (int i = 0; i < 8; i++)
                #pragma unroll
                for (int j = 0; j < 4; j++)
                    acc2[i][j] = fmaf(pa[i], bv[j], acc2[i][j]);
        }
        // fused bf16 split store: HdH/HdL, layout [s*128+r][512]
        #pragma unroll
        for (int i = 0; i < 8; i++) {
            int r = (i < 4) ? (ty * 4 + i) : (64 + ty * 4 + (i - 4));
            size_t base = ((size_t)s * 128 + r) * 512 + cc * 64 + tx * 4;
            __nv_bfloat16 h0,h1,h2,h3,l0,l1,l2,l3;
            split1(acc2[i][0],h0,l0); split1(acc2[i][1],h1,l1);
            split1(acc2[i][2],h2,l2); split1(acc2[i][3],h3,l3);
            __nv_bfloat162 t;
            t.x=h0; t.y=h1; *(__nv_bfloat162*)(g_HdH+base)   = t;
            t.x=h2; t.y=h3; *(__nv_bfloat162*)(g_HdH+base+2) = t;
            t.x=l0; t.y=l1; *(__nv_bfloat162*)(g_HdL+base)   = t;
            t.x=l2; t.y=l3; *(__nv_bfloat162*)(g_HdL+base+2) = t;
        }
    }
}

// ---------------------------------------------------------------------------
extern "C" void kernel_launch(void* const* d_in, const int* in_sizes, int n_in,
                              void* d_out, int out_size)
{
    (void)in_sizes; (void)n_in; (void)out_size;
    const float* h    = (const float*)d_in[0];
    const float* hOpp = (const float*)d_in[1];
    const float* Wq   = (const float*)d_in[2];
    const float* Wk   = (const float*)d_in[3];
    const float* Wv   = (const float*)d_in[4];
    const float* Wout = (const float*)d_in[5];
    float* out = (float*)d_out;

    cudaFuncSetAttribute(gemm_hmma,
                         cudaFuncAttributeMaxDynamicSharedMemorySize, GEMM_SMEM);
    cudaFuncSetAttribute(attn_kernel,
                         cudaFuncAttributeMaxDynamicSharedMemorySize, ATTN_SMEM);

    split_x <<<dim3(16384, 2), 256>>>(h, hOpp);
    wsplit  <<<dim3(512, 3), 256>>>(Wq, Wk, Wv);
    wosplit <<<512, 512>>>(Wout);

    gemm_hmma<<<dim3(512, 4, 3), 256, GEMM_SMEM>>>(-1, nullptr);  // K, Q, V projections

    attn_kernel<<<512, 256, ATTN_SMEM>>>();

    gemm_hmma<<<dim3(512, 4, 1), 256, GEMM_SMEM>>>(3, out);       // out = Hd @ Wout
}

// round 9
// speedup vs baseline: 2.0467x; 1.1090x over previous
#include <cuda_runtime.h>
#include <cuda_bf16.h>
#include <cstdint>

#define SA 65536

// ---------------- scratch (static device globals) --------------------------
__device__ __nv_bfloat16 g_hH[(size_t)SA * 256], g_hL[(size_t)SA * 256];
__device__ __nv_bfloat16 g_oH[(size_t)SA * 256], g_oL[(size_t)SA * 256];
__device__ __nv_bfloat16 g_WtH[3][512 * 256], g_WtL[3][512 * 256]; // 0=K,1=Q,2=V : [n][d]
__device__ __nv_bfloat16 g_WoH[512 * 512],  g_WoL[512 * 512];      // [e][n]
// projections, bf16 split, layout [n][h*64+k]
__device__ __nv_bfloat16 g_KH[(size_t)SA * 512], g_KL[(size_t)SA * 512];
__device__ __nv_bfloat16 g_QH[(size_t)SA * 512], g_QL[(size_t)SA * 512];
__device__ __nv_bfloat16 g_VH[(size_t)SA * 512], g_VL[(size_t)SA * 512];
__device__ __nv_bfloat16 g_HdH[(size_t)SA * 512], g_HdL[(size_t)SA * 512];

// ---------------- helpers ---------------------------------------------------
__device__ __forceinline__ void split1(float x, __nv_bfloat16& hi, __nv_bfloat16& lo) {
    hi = __float2bfloat16(x);
    lo = __float2bfloat16(x - __bfloat162float(hi));
}
__device__ __forceinline__ uint32_t s2u(const void* p) {
    uint32_t a;
    asm("{ .reg .u64 t; cvta.to.shared.u64 t, %1; cvt.u32.u64 %0, t; }" : "=r"(a) : "l"(p));
    return a;
}
__device__ __forceinline__ void ldsm4(uint32_t addr, uint32_t& r0, uint32_t& r1,
                                      uint32_t& r2, uint32_t& r3) {
    asm volatile("ldmatrix.sync.aligned.m8n8.x4.shared.b16 {%0,%1,%2,%3}, [%4];"
                 : "=r"(r0), "=r"(r1), "=r"(r2), "=r"(r3) : "r"(addr));
}
__device__ __forceinline__ void ldsm2(uint32_t addr, uint32_t& r0, uint32_t& r1) {
    asm volatile("ldmatrix.sync.aligned.m8n8.x2.shared.b16 {%0,%1}, [%2];"
                 : "=r"(r0), "=r"(r1) : "r"(addr));
}
__device__ __forceinline__ void ldsm2t(uint32_t addr, uint32_t& r0, uint32_t& r1) {
    asm volatile("ldmatrix.sync.aligned.m8n8.x2.trans.shared.b16 {%0,%1}, [%2];"
                 : "=r"(r0), "=r"(r1) : "r"(addr));
}
__device__ __forceinline__ void mma16816(float& c0, float& c1, float& c2, float& c3,
                                         uint32_t a0, uint32_t a1, uint32_t a2, uint32_t a3,
                                         uint32_t b0, uint32_t b1) {
    asm volatile(
        "mma.sync.aligned.m16n8k16.row.col.f32.bf16.bf16.f32 "
        "{%0,%1,%2,%3}, {%4,%5,%6,%7}, {%8,%9}, {%0,%1,%2,%3};"
        : "+f"(c0), "+f"(c1), "+f"(c2), "+f"(c3)
        : "r"(a0), "r"(a1), "r"(a2), "r"(a3), "r"(b0), "r"(b1));
}
__device__ __forceinline__ void cp16(uint32_t dst, const void* src) {
    asm volatile("cp.async.cg.shared.global [%0], [%1], 16;"
                 :: "r"(dst), "l"(__cvta_generic_to_global(src)));
}
__device__ __forceinline__ void cp_commit() {
    asm volatile("cp.async.commit_group;" ::: "memory");
}
template <int N>
__device__ __forceinline__ void cp_wait() {
    asm volatile("cp.async.wait_group %0;" :: "n"(N) : "memory");
}

// ---------------- split kernels --------------------------------------------
__global__ __launch_bounds__(256) void split_x(const float* __restrict__ h,
                                               const float* __restrict__ ho) {
    size_t i = ((size_t)blockIdx.x * 256 + threadIdx.x) * 4;
    const float* src = blockIdx.y ? ho : h;
    __nv_bfloat16* dh = blockIdx.y ? g_oH : g_hH;
    __nv_bfloat16* dl = blockIdx.y ? g_oL : g_hL;
    float4 v = *(const float4*)(src + i);
    __nv_bfloat16 a0,a1,a2,a3,b0,b1,b2,b3;
    split1(v.x,a0,b0); split1(v.y,a1,b1); split1(v.z,a2,b2); split1(v.w,a3,b3);
    __nv_bfloat162 t;
    t.x=a0; t.y=a1; *(__nv_bfloat162*)(dh+i)   = t;
    t.x=a2; t.y=a3; *(__nv_bfloat162*)(dh+i+2) = t;
    t.x=b0; t.y=b1; *(__nv_bfloat162*)(dl+i)   = t;
    t.x=b2; t.y=b3; *(__nv_bfloat162*)(dl+i+2) = t;
}

__global__ void wsplit(const float* __restrict__ Wq, const float* __restrict__ Wk,
                       const float* __restrict__ Wv) {
    int n = blockIdx.x;          // 0..511  (= h*64+k)
    int d = threadIdx.x;         // 0..255
    int m = blockIdx.y;          // 0=K,1=Q,2=V
    const float* W = (m == 0) ? Wk : ((m == 1) ? Wq : Wv);
    float w = W[(n >> 6) * 16384 + d * 64 + (n & 63)];
    __nv_bfloat16 hi, lo; split1(w, hi, lo);
    g_WtH[m][n * 256 + d] = hi;
    g_WtL[m][n * 256 + d] = lo;
}

__global__ void wosplit(const float* __restrict__ Wo) {
    int e = blockIdx.x;          // 0..511 output col
    int n = threadIdx.x;         // 0..511 input (h*64+k)
    float w = Wo[n * 512 + e];
    __nv_bfloat16 hi, lo; split1(w, hi, lo);
    g_WoH[e * 512 + n] = hi;
    g_WoL[e * 512 + n] = lo;
}

// ---------------- HMMA GEMM: C(65536x512) = (Ah+Al) @ (Bh+Bl)^T -------------
// modes 0-2: write bf16 split (KH/KL, QH/QL, VH/VL). mode 3: fp32 out.
#define RS      80          // smem row stride bytes (40 bf16)
#define MATB    10240       // 128 rows * 80B
#define STAGE   40960       // 4 matrices
#define GEMM_SMEM (2 * STAGE)

__global__ __launch_bounds__(256, 2) void gemm_hmma(int modeSel, float* __restrict__ outp)
{
    extern __shared__ char smc[];
    int mode = (modeSel < 0) ? (int)blockIdx.z : modeSel;

    const __nv_bfloat16 *Ah, *Al, *Bh, *Bl; int kdim;
    __nv_bfloat16 *CH = nullptr, *CL = nullptr;
    if      (mode == 0) { Ah=g_hH;  Al=g_hL;  Bh=g_WtH[0]; Bl=g_WtL[0]; CH=g_KH; CL=g_KL; kdim=256; }
    else if (mode == 1) { Ah=g_oH;  Al=g_oL;  Bh=g_WtH[1]; Bl=g_WtL[1]; CH=g_QH; CL=g_QL; kdim=256; }
    else if (mode == 2) { Ah=g_oH;  Al=g_oL;  Bh=g_WtH[2]; Bl=g_WtL[2]; CH=g_VH; CL=g_VL; kdim=256; }
    else                { Ah=g_HdH; Al=g_HdL; Bh=g_WoH;    Bl=g_WoL;    kdim=512; }

    const int tid  = threadIdx.x;
    const int lane = tid & 31;
    const int wid  = tid >> 5;
    const int wm   = (wid >> 2) * 64;
    const int wn   = (wid & 3) * 32;
    const int row0 = blockIdx.x * 128;
    const int n0   = blockIdx.y * 128;
    const int nch  = kdim >> 5;

    const uint32_t sb = s2u(smc);
    const __nv_bfloat16* srcs[4] = { Ah + (size_t)row0 * kdim, Al + (size_t)row0 * kdim,
                                     Bh + (size_t)n0   * kdim, Bl + (size_t)n0   * kdim };

    auto load_chunk = [&](int i, int st) {
        uint32_t sbase = sb + st * STAGE;
        size_t k0 = (size_t)i * 32;
        #pragma unroll
        for (int it = 0; it < 8; it++) {
            int g   = it * 256 + tid;
            int mat = g >> 9;
            int rem = g & 511;
            int r   = rem >> 2, j = rem & 3;
            cp16(sbase + mat * MATB + r * RS + j * 16,
                 srcs[mat] + (size_t)r * kdim + k0 + j * 8);
        }
    };

    float c[4][4][4];
    #pragma unroll
    for (int mt = 0; mt < 4; mt++)
        #pragma unroll
        for (int nt = 0; nt < 4; nt++)
            #pragma unroll
            for (int q = 0; q < 4; q++) c[mt][nt][q] = 0.f;

    load_chunk(0, 0); cp_commit();

    const int a_row = lane & 15, a_hk = (lane >> 4) * 16;
    const int b_row = lane & 7,  b_hk = ((lane >> 3) & 1) * 16;

    for (int i = 0; i < nch; i++) {
        if (i + 1 < nch) { load_chunk(i + 1, (i + 1) & 1); cp_commit(); cp_wait<1>(); }
        else             { cp_wait<0>(); }
        __syncthreads();

        uint32_t stb = sb + (i & 1) * STAGE;
        #pragma unroll
        for (int ks = 0; ks < 2; ks++) {
            uint32_t a_h[4][4];
            uint32_t aAddrH = stb + (wm + a_row) * RS + ks * 32 + a_hk;
            uint32_t aAddrL = aAddrH + MATB;
            uint32_t bAddrH = stb + 2 * MATB + (wn + b_row) * RS + ks * 32 + b_hk;
            uint32_t bAddrL = bAddrH + MATB;

            #pragma unroll
            for (int mt = 0; mt < 4; mt++)
                ldsm4(aAddrH + mt * 16 * RS, a_h[mt][0], a_h[mt][1], a_h[mt][2], a_h[mt][3]);
            #pragma unroll
            for (int nt = 0; nt < 4; nt++) {
                uint32_t b0, b1;
                ldsm2(bAddrH + nt * 8 * RS, b0, b1);
                #pragma unroll
                for (int mt = 0; mt < 4; mt++)
                    mma16816(c[mt][nt][0], c[mt][nt][1], c[mt][nt][2], c[mt][nt][3],
                             a_h[mt][0], a_h[mt][1], a_h[mt][2], a_h[mt][3], b0, b1);
            }
            #pragma unroll
            for (int nt = 0; nt < 4; nt++) {
                uint32_t b0, b1;
                ldsm2(bAddrL + nt * 8 * RS, b0, b1);
                #pragma unroll
                for (int mt = 0; mt < 4; mt++)
                    mma16816(c[mt][nt][0], c[mt][nt][1], c[mt][nt][2], c[mt][nt][3],
                             a_h[mt][0], a_h[mt][1], a_h[mt][2], a_h[mt][3], b0, b1);
            }
            #pragma unroll
            for (int mt = 0; mt < 4; mt++)
                ldsm4(aAddrL + mt * 16 * RS, a_h[mt][0], a_h[mt][1], a_h[mt][2], a_h[mt][3]);
            #pragma unroll
            for (int nt = 0; nt < 4; nt++) {
                uint32_t b0, b1;
                ldsm2(bAddrH + nt * 8 * RS, b0, b1);
                #pragma unroll
                for (int mt = 0; mt < 4; mt++)
                    mma16816(c[mt][nt][0], c[mt][nt][1], c[mt][nt][2], c[mt][nt][3],
                             a_h[mt][0], a_h[mt][1], a_h[mt][2], a_h[mt][3], b0, b1);
            }
        }
        __syncthreads();
    }

    // epilogue
    if (mode < 3) {
        #pragma unroll
        for (int mt = 0; mt < 4; mt++) {
            int rg = row0 + wm + mt * 16 + (lane >> 2);
            #pragma unroll
            for (int nt = 0; nt < 4; nt++) {
                int cg = n0 + wn + nt * 8 + 2 * (lane & 3);
                __nv_bfloat16 h0,h1,h2,h3,l0,l1,l2,l3;
                split1(c[mt][nt][0],h0,l0); split1(c[mt][nt][1],h1,l1);
                split1(c[mt][nt][2],h2,l2); split1(c[mt][nt][3],h3,l3);
                __nv_bfloat162 t;
                t.x=h0; t.y=h1; *(__nv_bfloat162*)(CH + (size_t)rg * 512 + cg)       = t;
                t.x=l0; t.y=l1; *(__nv_bfloat162*)(CL + (size_t)rg * 512 + cg)       = t;
                t.x=h2; t.y=h3; *(__nv_bfloat162*)(CH + (size_t)(rg + 8) * 512 + cg) = t;
                t.x=l2; t.y=l3; *(__nv_bfloat162*)(CL + (size_t)(rg + 8) * 512 + cg) = t;
            }
        }
    } else {
        #pragma unroll
        for (int mt = 0; mt < 4; mt++) {
            int rg = row0 + wm + mt * 16 + (lane >> 2);
            #pragma unroll
            for (int nt = 0; nt < 4; nt++) {
                int cg = n0 + wn + nt * 8 + 2 * (lane & 3);
                *(float2*)(outp + (size_t)rg * 512 + cg)       = make_float2(c[mt][nt][0], c[mt][nt][1]);
                *(float2*)(outp + (size_t)(rg + 8) * 512 + cg) = make_float2(c[mt][nt][2], c[mt][nt][3]);
            }
        }
    }
}

// ---------------- HMMA attention --------------------------------------------
// Per tile s (head=s>>6, b=s&63): C = Kv@Qv^T *0.125; P = softmax; Hd = P@Vv.
// Kv/Qv/Vv rows are [b*1024 + a*8 + (c>>6)][head*64 + (c&63)] of the split arrays.
#define TK      18432       // 128 rows * 144B (72 bf16, padded)
#define CF_STR  132         // fp32 logits row stride (floats)
#define P_STR   136         // P row stride (bf16)
#define OFF_P   73728
#define P_BYTES 34816       // 128 * 136 * 2
#define OFF_V   143360
#define ATTN_SMEM 180224    // OFF_V + 2*TK

__global__ __launch_bounds__(256, 1) void attn_hmma()
{
    extern __shared__ char smc[];
    const uint32_t sb = s2u(smc);
    float* Cf = (float*)smc;                       // overlays K/Q tiles

    const int s = blockIdx.x;
    const int head = s >> 6;
    const int b = s & 63;
    const size_t tbase = ((size_t)b * 1024) * 512 + head * 64;

    const int tid  = threadIdx.x;
    const int lane = tid & 31;
    const int wid  = tid >> 5;
    const int a_row = lane & 15, a_hk = (lane >> 4) * 16;
    const int b_row = lane & 7,  b_hk = ((lane >> 3) & 1) * 16;

    // ================= phase 1: C = Kv @ Qv^T ============================
    const int wm = (wid >> 2) * 64;     // 2x4 warps, warp 64x32
    const int wn = (wid & 3) * 32;

    float c1[4][4][4];
    #pragma unroll
    for (int mt = 0; mt < 4; mt++)
        #pragma unroll
        for (int nt = 0; nt < 4; nt++)
            #pragma unroll
            for (int q = 0; q < 4; q++) c1[mt][nt][q] = 0.f;

    for (int kc = 0; kc < 8; kc++) {
        __syncthreads();
        const size_t off = tbase + (size_t)kc * 512;
        const __nv_bfloat16* srcs[4] = { g_KH + off, g_KL + off, g_QH + off, g_QL + off };
        #pragma unroll
        for (int it = 0; it < 16; it++) {
            int g = it * 256 + tid;
            int mat = g >> 10;
            int rem = g & 1023;
            int r = rem >> 3, j = rem & 7;
            cp16(sb + mat * TK + r * 144 + j * 16, srcs[mat] + (size_t)r * 4096 + j * 8);
        }
        cp_commit(); cp_wait<0>();
        __syncthreads();

        #pragma unroll
        for (int ks = 0; ks < 4; ks++) {
            uint32_t ah[4][4], al[4][4], bh[4][2], bl[4][2];
            uint32_t aH = sb + (wm + a_row) * 144 + ks * 32 + a_hk;
            uint32_t aL = aH + TK;
            uint32_t bH = sb + 2 * TK + (wn + b_row) * 144 + ks * 32 + b_hk;
            uint32_t bL = bH + TK;
            #pragma unroll
            for (int mt = 0; mt < 4; mt++)
                ldsm4(aH + mt * 16 * 144, ah[mt][0], ah[mt][1], ah[mt][2], ah[mt][3]);
            #pragma unroll
            for (int nt = 0; nt < 4; nt++)
                ldsm2(bH + nt * 8 * 144, bh[nt][0], bh[nt][1]);
            #pragma unroll
            for (int nt = 0; nt < 4; nt++)
                #pragma unroll
                for (int mt = 0; mt < 4; mt++)
                    mma16816(c1[mt][nt][0], c1[mt][nt][1], c1[mt][nt][2], c1[mt][nt][3],
                             ah[mt][0], ah[mt][1], ah[mt][2], ah[mt][3], bh[nt][0], bh[nt][1]);
            #pragma unroll
            for (int nt = 0; nt < 4; nt++)
                ldsm2(bL + nt * 8 * 144, bl[nt][0], bl[nt][1]);
            #pragma unroll
            for (int nt = 0; nt < 4; nt++)
                #pragma unroll
                for (int mt = 0; mt < 4; mt++)
                    mma16816(c1[mt][nt][0], c1[mt][nt][1], c1[mt][nt][2], c1[mt][nt][3],
                             ah[mt][0], ah[mt][1], ah[mt][2], ah[mt][3], bl[nt][0], bl[nt][1]);
            #pragma unroll
            for (int mt = 0; mt < 4; mt++)
                ldsm4(aL + mt * 16 * 144, al[mt][0], al[mt][1], al[mt][2], al[mt][3]);
            #pragma unroll
            for (int nt = 0; nt < 4; nt++)
                #pragma unroll
                for (int mt = 0; mt < 4; mt++)
                    mma16816(c1[mt][nt][0], c1[mt][nt][1], c1[mt][nt][2], c1[mt][nt][3],
                             al[mt][0], al[mt][1], al[mt][2], al[mt][3], bh[nt][0], bh[nt][1]);
        }
    }

    // write scaled logits to smem
    __syncthreads();
    const float norm = 0.125f;
    #pragma unroll
    for (int mt = 0; mt < 4; mt++) {
        int rg = wm + mt * 16 + (lane >> 2);
        #pragma unroll
        for (int nt = 0; nt < 4; nt++) {
            int cg = wn + nt * 8 + 2 * (lane & 3);
            *(float2*)(Cf + rg * CF_STR + cg) =
                make_float2(c1[mt][nt][0] * norm, c1[mt][nt][1] * norm);
            *(float2*)(Cf + (rg + 8) * CF_STR + cg) =
                make_float2(c1[mt][nt][2] * norm, c1[mt][nt][3] * norm);
        }
    }
    __syncthreads();

    // ================= softmax: 2 threads per row ========================
    {
        int row = tid >> 1, half = tid & 1;
        float* crow = Cf + row * CF_STR + half * 64;
        float m = -1e30f;
        #pragma unroll
        for (int j = 0; j < 16; j++) {
            float4 v = *(float4*)(crow + j * 4);
            m = fmaxf(m, fmaxf(fmaxf(v.x, v.y), fmaxf(v.z, v.w)));
        }
        m = fmaxf(m, __shfl_xor_sync(0xffffffffu, m, 1));
        float ssum = 0.f;
        #pragma unroll
        for (int j = 0; j < 16; j++) {
            float4 v = *(float4*)(crow + j * 4);
            v.x = __expf(v.x - m); v.y = __expf(v.y - m);
            v.z = __expf(v.z - m); v.w = __expf(v.w - m);
            ssum += (v.x + v.y) + (v.z + v.w);
            *(float4*)(crow + j * 4) = v;
        }
        ssum += __shfl_xor_sync(0xffffffffu, ssum, 1);
        float inv = 1.f / ssum;
        __nv_bfloat16* ph = (__nv_bfloat16*)(smc + OFF_P) + row * P_STR + half * 64;
        __nv_bfloat16* pl = ph + (P_BYTES / 2);
        #pragma unroll
        for (int j = 0; j < 16; j++) {
            float4 v = *(float4*)(crow + j * 4);
            __nv_bfloat16 h0,h1,h2,h3,l0,l1,l2,l3;
            split1(v.x * inv, h0, l0); split1(v.y * inv, h1, l1);
            split1(v.z * inv, h2, l2); split1(v.w * inv, h3, l3);
            __nv_bfloat162 t;
            t.x=h0; t.y=h1; *(__nv_bfloat162*)(ph + j * 4)     = t;
            t.x=h2; t.y=h3; *(__nv_bfloat162*)(ph + j * 4 + 2) = t;
            t.x=l0; t.y=l1; *(__nv_bfloat162*)(pl + j * 4)     = t;
            t.x=l2; t.y=l3; *(__nv_bfloat162*)(pl + j * 4 + 2) = t;
        }
    }

    // ================= phase 2: Hd = P @ Vv ==============================
    const int wm2 = (wid >> 2) * 64;    // 2x4 warps, warp 64x16 per 64-col chunk
    const int wn2 = (wid & 3) * 16;
    const int v_row = lane & 15;

    for (int cc = 0; cc < 8; cc++) {
        __syncthreads();    // prev chunk MMAs done with sV; cc=0: sP visible
        const size_t voff = tbase + (size_t)cc * 512;
        const __nv_bfloat16* vsrc[2] = { g_VH + voff, g_VL + voff };
        #pragma unroll
        for (int it = 0; it < 8; it++) {
            int g = it * 256 + tid;
            int mat = g >> 10;
            int rem = g & 1023;
            int r = rem >> 3, j = rem & 7;
            cp16(sb + OFF_V + mat * TK + r * 144 + j * 16, vsrc[mat] + (size_t)r * 4096 + j * 8);
        }
        cp_commit(); cp_wait<0>();
        __syncthreads();

        float c2[4][2][4];
        #pragma unroll
        for (int mt = 0; mt < 4; mt++)
            #pragma unroll
            for (int nt = 0; nt < 2; nt++)
                #pragma unroll
                for (int q = 0; q < 4; q++) c2[mt][nt][q] = 0.f;

        #pragma unroll
        for (int ks = 0; ks < 8; ks++) {
            uint32_t ph[4][4], pl[4][4], vh[2][2], vl[2][2];
            uint32_t pH = sb + OFF_P + (wm2 + a_row) * 272 + ks * 32 + a_hk;
            uint32_t pL = pH + P_BYTES;
            uint32_t vH = sb + OFF_V + (ks * 16 + v_row) * 144 + wn2 * 2;
            uint32_t vL = vH + TK;
            #pragma unroll
            for (int mt = 0; mt < 4; mt++)
                ldsm4(pH + mt * 16 * 272, ph[mt][0], ph[mt][1], ph[mt][2], ph[mt][3]);
            #pragma unroll
            for (int nt = 0; nt < 2; nt++)
                ldsm2t(vH + nt * 16, vh[nt][0], vh[nt][1]);
            #pragma unroll
            for (int nt = 0; nt < 2; nt++)
                #pragma unroll
                for (int mt = 0; mt < 4; mt++)
                    mma16816(c2[mt][nt][0], c2[mt][nt][1], c2[mt][nt][2], c2[mt][nt][3],
                             ph[mt][0], ph[mt][1], ph[mt][2], ph[mt][3], vh[nt][0], vh[nt][1]);
            #pragma unroll
            for (int nt = 0; nt < 2; nt++)
                ldsm2t(vL + nt * 16, vl[nt][0], vl[nt][1]);
            #pragma unroll
            for (int nt = 0; nt < 2; nt++)
                #pragma unroll
                for (int mt = 0; mt < 4; mt++)
                    mma16816(c2[mt][nt][0], c2[mt][nt][1], c2[mt][nt][2], c2[mt][nt][3],
                             ph[mt][0], ph[mt][1], ph[mt][2], ph[mt][3], vl[nt][0], vl[nt][1]);
            #pragma unroll
            for (int mt = 0; mt < 4; mt++)
                ldsm4(pL + mt * 16 * 272, pl[mt][0], pl[mt][1], pl[mt][2], pl[mt][3]);
            #pragma unroll
            for (int nt = 0; nt < 2; nt++)
                #pragma unroll
                for (int mt = 0; mt < 4; mt++)
                    mma16816(c2[mt][nt][0], c2[mt][nt][1], c2[mt][nt][2], c2[mt][nt][3],
                             pl[mt][0], pl[mt][1], pl[mt][2], pl[mt][3], vh[nt][0], vh[nt][1]);
        }

        // store Hd bf16 split
        #pragma unroll
        for (int mt = 0; mt < 4; mt++) {
            int rg = wm2 + mt * 16 + (lane >> 2);
            #pragma unroll
            for (int nt = 0; nt < 2; nt++) {
                int cg = cc * 64 + wn2 + nt * 8 + 2 * (lane & 3);
                size_t base0 = ((size_t)s * 128 + rg) * 512 + cg;
                size_t base1 = base0 + 8 * 512;
                __nv_bfloat16 h0,h1,h2,h3,l0,l1,l2,l3;
                split1(c2[mt][nt][0],h0,l0); split1(c2[mt][nt][1],h1,l1);
                split1(c2[mt][nt][2],h2,l2); split1(c2[mt][nt][3],h3,l3);
                __nv_bfloat162 t;
                t.x=h0; t.y=h1; *(__nv_bfloat162*)(g_HdH + base0) = t;
                t.x=l0; t.y=l1; *(__nv_bfloat162*)(g_HdL + base0) = t;
                t.x=h2; t.y=h3; *(__nv_bfloat162*)(g_HdH + base1) = t;
                t.x=l2; t.y=l3; *(__nv_bfloat162*)(g_HdL + base1) = t;
            }
        }
    }
}

// ---------------------------------------------------------------------------
extern "C" void kernel_launch(void* const* d_in, const int* in_sizes, int n_in,
                              void* d_out, int out_size)
{
    (void)in_sizes; (void)n_in; (void)out_size;
    const float* h    = (const float*)d_in[0];
    const float* hOpp = (const float*)d_in[1];
    const float* Wq   = (const float*)d_in[2];
    const float* Wk   = (const float*)d_in[3];
    const float* Wv   = (const float*)d_in[4];
    const float* Wout = (const float*)d_in[5];
    float* out = (float*)d_out;

    cudaFuncSetAttribute(gemm_hmma,
                         cudaFuncAttributeMaxDynamicSharedMemorySize, GEMM_SMEM);
    cudaFuncSetAttribute(attn_hmma,
                         cudaFuncAttributeMaxDynamicSharedMemorySize, ATTN_SMEM);

    split_x <<<dim3(16384, 2), 256>>>(h, hOpp);
    wsplit  <<<dim3(512, 3), 256>>>(Wq, Wk, Wv);
    wosplit <<<512, 512>>>(Wout);

    gemm_hmma<<<dim3(512, 4, 3), 256, GEMM_SMEM>>>(-1, nullptr);  // K, Q, V projections

    attn_hmma<<<512, 256, ATTN_SMEM>>>();

    gemm_hmma<<<dim3(512, 4, 1), 256, GEMM_SMEM>>>(3, out);       // out = Hd @ Wout
}

// round 10
// speedup vs baseline: 2.2182x; 1.0838x over previous
#include <cuda_runtime.h>
#include <cuda_bf16.h>
#include <cstdint>

#define SA 65536

// ---------------- scratch (static device globals) --------------------------
__device__ __nv_bfloat16 g_hH[(size_t)SA * 256], g_hL[(size_t)SA * 256];
__device__ __nv_bfloat16 g_oH[(size_t)SA * 256], g_oL[(size_t)SA * 256];
__device__ __nv_bfloat16 g_WtH[3][512 * 256], g_WtL[3][512 * 256]; // 0=K,1=Q,2=V : [n][d]
__device__ __nv_bfloat16 g_WoH[512 * 512],  g_WoL[512 * 512];      // [e][n]
// projections, bf16 split, layout [n][h*64+k]
__device__ __nv_bfloat16 g_KH[(size_t)SA * 512], g_KL[(size_t)SA * 512];
__device__ __nv_bfloat16 g_QH[(size_t)SA * 512], g_QL[(size_t)SA * 512];
__device__ __nv_bfloat16 g_VH[(size_t)SA * 512], g_VL[(size_t)SA * 512];
__device__ __nv_bfloat16 g_HdH[(size_t)SA * 512], g_HdL[(size_t)SA * 512];

// ---------------- helpers ---------------------------------------------------
__device__ __forceinline__ void split1(float x, __nv_bfloat16& hi, __nv_bfloat16& lo) {
    hi = __float2bfloat16(x);
    lo = __float2bfloat16(x - __bfloat162float(hi));
}
__device__ __forceinline__ uint32_t s2u(const void* p) {
    uint32_t a;
    asm("{ .reg .u64 t; cvta.to.shared.u64 t, %1; cvt.u32.u64 %0, t; }" : "=r"(a) : "l"(p));
    return a;
}
__device__ __forceinline__ void ldsm4(uint32_t addr, uint32_t& r0, uint32_t& r1,
                                      uint32_t& r2, uint32_t& r3) {
    asm volatile("ldmatrix.sync.aligned.m8n8.x4.shared.b16 {%0,%1,%2,%3}, [%4];"
                 : "=r"(r0), "=r"(r1), "=r"(r2), "=r"(r3) : "r"(addr));
}
__device__ __forceinline__ void ldsm2(uint32_t addr, uint32_t& r0, uint32_t& r1) {
    asm volatile("ldmatrix.sync.aligned.m8n8.x2.shared.b16 {%0,%1}, [%2];"
                 : "=r"(r0), "=r"(r1) : "r"(addr));
}
__device__ __forceinline__ void ldsm2t(uint32_t addr, uint32_t& r0, uint32_t& r1) {
    asm volatile("ldmatrix.sync.aligned.m8n8.x2.trans.shared.b16 {%0,%1}, [%2];"
                 : "=r"(r0), "=r"(r1) : "r"(addr));
}
__device__ __forceinline__ void mma16816(float& c0, float& c1, float& c2, float& c3,
                                         uint32_t a0, uint32_t a1, uint32_t a2, uint32_t a3,
                                         uint32_t b0, uint32_t b1) {
    asm volatile(
        "mma.sync.aligned.m16n8k16.row.col.f32.bf16.bf16.f32 "
        "{%0,%1,%2,%3}, {%4,%5,%6,%7}, {%8,%9}, {%0,%1,%2,%3};"
        : "+f"(c0), "+f"(c1), "+f"(c2), "+f"(c3)
        : "r"(a0), "r"(a1), "r"(a2), "r"(a3), "r"(b0), "r"(b1));
}
__device__ __forceinline__ void cp16(uint32_t dst, const void* src) {
    asm volatile("cp.async.cg.shared.global [%0], [%1], 16;"
                 :: "r"(dst), "l"(__cvta_generic_to_global(src)));
}
__device__ __forceinline__ void cp_commit() {
    asm volatile("cp.async.commit_group;" ::: "memory");
}
template <int N>
__device__ __forceinline__ void cp_wait() {
    asm volatile("cp.async.wait_group %0;" :: "n"(N) : "memory");
}

// ---------------- split kernels --------------------------------------------
__global__ __launch_bounds__(256) void split_x(const float* __restrict__ h,
                                               const float* __restrict__ ho) {
    size_t i = ((size_t)blockIdx.x * 256 + threadIdx.x) * 4;
    const float* src = blockIdx.y ? ho : h;
    __nv_bfloat16* dh = blockIdx.y ? g_oH : g_hH;
    __nv_bfloat16* dl = blockIdx.y ? g_oL : g_hL;
    float4 v = *(const float4*)(src + i);
    __nv_bfloat16 a0,a1,a2,a3,b0,b1,b2,b3;
    split1(v.x,a0,b0); split1(v.y,a1,b1); split1(v.z,a2,b2); split1(v.w,a3,b3);
    __nv_bfloat162 t;
    t.x=a0; t.y=a1; *(__nv_bfloat162*)(dh+i)   = t;
    t.x=a2; t.y=a3; *(__nv_bfloat162*)(dh+i+2) = t;
    t.x=b0; t.y=b1; *(__nv_bfloat162*)(dl+i)   = t;
    t.x=b2; t.y=b3; *(__nv_bfloat162*)(dl+i+2) = t;
}

__global__ void wsplit(const float* __restrict__ Wq, const float* __restrict__ Wk,
                       const float* __restrict__ Wv) {
    int n = blockIdx.x;          // 0..511  (= h*64+k)
    int d = threadIdx.x;         // 0..255
    int m = blockIdx.y;          // 0=K,1=Q,2=V
    const float* W = (m == 0) ? Wk : ((m == 1) ? Wq : Wv);
    float w = W[(n >> 6) * 16384 + d * 64 + (n & 63)];
    __nv_bfloat16 hi, lo; split1(w, hi, lo);
    g_WtH[m][n * 256 + d] = hi;
    g_WtL[m][n * 256 + d] = lo;
}

__global__ void wosplit(const float* __restrict__ Wo) {
    int e = blockIdx.x;          // 0..511 output col
    int n = threadIdx.x;         // 0..511 input (h*64+k)
    float w = Wo[n * 512 + e];
    __nv_bfloat16 hi, lo; split1(w, hi, lo);
    g_WoH[e * 512 + n] = hi;
    g_WoL[e * 512 + n] = lo;
}

// ---------------- HMMA GEMM: C(65536x512) = (Ah+Al) @ (Bh+Bl)^T -------------
// modes 0-2: write bf16 split (KH/KL, QH/QL, VH/VL). mode 3: fp32 out.
#define RS      80          // smem row stride bytes (40 bf16)
#define MATB    10240       // 128 rows * 80B
#define STAGE   40960       // 4 matrices
#define GEMM_SMEM (2 * STAGE)

__global__ __launch_bounds__(256, 2) void gemm_hmma(int modeSel, float* __restrict__ outp)
{
    extern __shared__ char smc[];
    int mode = (modeSel < 0) ? (int)blockIdx.z : modeSel;

    const __nv_bfloat16 *Ah, *Al, *Bh, *Bl; int kdim;
    __nv_bfloat16 *CH = nullptr, *CL = nullptr;
    if      (mode == 0) { Ah=g_hH;  Al=g_hL;  Bh=g_WtH[0]; Bl=g_WtL[0]; CH=g_KH; CL=g_KL; kdim=256; }
    else if (mode == 1) { Ah=g_oH;  Al=g_oL;  Bh=g_WtH[1]; Bl=g_WtL[1]; CH=g_QH; CL=g_QL; kdim=256; }
    else if (mode == 2) { Ah=g_oH;  Al=g_oL;  Bh=g_WtH[2]; Bl=g_WtL[2]; CH=g_VH; CL=g_VL; kdim=256; }
    else                { Ah=g_HdH; Al=g_HdL; Bh=g_WoH;    Bl=g_WoL;    kdim=512; }

    const int tid  = threadIdx.x;
    const int lane = tid & 31;
    const int wid  = tid >> 5;
    const int wm   = (wid >> 2) * 64;
    const int wn   = (wid & 3) * 32;
    const int row0 = blockIdx.x * 128;
    const int n0   = blockIdx.y * 128;
    const int nch  = kdim >> 5;

    const uint32_t sb = s2u(smc);
    const __nv_bfloat16* srcs[4] = { Ah + (size_t)row0 * kdim, Al + (size_t)row0 * kdim,
                                     Bh + (size_t)n0   * kdim, Bl + (size_t)n0   * kdim };

    auto load_chunk = [&](int i, int st) {
        uint32_t sbase = sb + st * STAGE;
        size_t k0 = (size_t)i * 32;
        #pragma unroll
        for (int it = 0; it < 8; it++) {
            int g   = it * 256 + tid;
            int mat = g >> 9;
            int rem = g & 511;
            int r   = rem >> 2, j = rem & 3;
            cp16(sbase + mat * MATB + r * RS + j * 16,
                 srcs[mat] + (size_t)r * kdim + k0 + j * 8);
        }
    };

    float c[4][4][4];
    #pragma unroll
    for (int mt = 0; mt < 4; mt++)
        #pragma unroll
        for (int nt = 0; nt < 4; nt++)
            #pragma unroll
            for (int q = 0; q < 4; q++) c[mt][nt][q] = 0.f;

    load_chunk(0, 0); cp_commit();

    const int a_row = lane & 15, a_hk = (lane >> 4) * 16;
    const int b_row = lane & 7,  b_hk = ((lane >> 3) & 1) * 16;

    for (int i = 0; i < nch; i++) {
        if (i + 1 < nch) { load_chunk(i + 1, (i + 1) & 1); cp_commit(); cp_wait<1>(); }
        else             { cp_wait<0>(); }
        __syncthreads();

        uint32_t stb = sb + (i & 1) * STAGE;
        #pragma unroll
        for (int ks = 0; ks < 2; ks++) {
            uint32_t a_h[4][4], bh[4][2], bl[4][2];
            uint32_t aAddrH = stb + (wm + a_row) * RS + ks * 32 + a_hk;
            uint32_t aAddrL = aAddrH + MATB;
            uint32_t bAddrH = stb + 2 * MATB + (wn + b_row) * RS + ks * 32 + b_hk;
            uint32_t bAddrL = bAddrH + MATB;

            // load both B splits once, reuse bh for pass 3
            #pragma unroll
            for (int nt = 0; nt < 4; nt++)
                ldsm2(bAddrH + nt * 8 * RS, bh[nt][0], bh[nt][1]);
            #pragma unroll
            for (int nt = 0; nt < 4; nt++)
                ldsm2(bAddrL + nt * 8 * RS, bl[nt][0], bl[nt][1]);
            #pragma unroll
            for (int mt = 0; mt < 4; mt++)
                ldsm4(aAddrH + mt * 16 * RS, a_h[mt][0], a_h[mt][1], a_h[mt][2], a_h[mt][3]);
            // pass 1: Ah * Bh
            #pragma unroll
            for (int nt = 0; nt < 4; nt++)
                #pragma unroll
                for (int mt = 0; mt < 4; mt++)
                    mma16816(c[mt][nt][0], c[mt][nt][1], c[mt][nt][2], c[mt][nt][3],
                             a_h[mt][0], a_h[mt][1], a_h[mt][2], a_h[mt][3], bh[nt][0], bh[nt][1]);
            // pass 2: Ah * Bl
            #pragma unroll
            for (int nt = 0; nt < 4; nt++)
                #pragma unroll
                for (int mt = 0; mt < 4; mt++)
                    mma16816(c[mt][nt][0], c[mt][nt][1], c[mt][nt][2], c[mt][nt][3],
                             a_h[mt][0], a_h[mt][1], a_h[mt][2], a_h[mt][3], bl[nt][0], bl[nt][1]);
            // pass 3: Al * Bh  (reload A, reuse bh)
            #pragma unroll
            for (int mt = 0; mt < 4; mt++)
                ldsm4(aAddrL + mt * 16 * RS, a_h[mt][0], a_h[mt][1], a_h[mt][2], a_h[mt][3]);
            #pragma unroll
            for (int nt = 0; nt < 4; nt++)
                #pragma unroll
                for (int mt = 0; mt < 4; mt++)
                    mma16816(c[mt][nt][0], c[mt][nt][1], c[mt][nt][2], c[mt][nt][3],
                             a_h[mt][0], a_h[mt][1], a_h[mt][2], a_h[mt][3], bh[nt][0], bh[nt][1]);
        }
        __syncthreads();
    }

    // epilogue
    if (mode < 3) {
        #pragma unroll
        for (int mt = 0; mt < 4; mt++) {
            int rg = row0 + wm + mt * 16 + (lane >> 2);
            #pragma unroll
            for (int nt = 0; nt < 4; nt++) {
                int cg = n0 + wn + nt * 8 + 2 * (lane & 3);
                __nv_bfloat16 h0,h1,h2,h3,l0,l1,l2,l3;
                split1(c[mt][nt][0],h0,l0); split1(c[mt][nt][1],h1,l1);
                split1(c[mt][nt][2],h2,l2); split1(c[mt][nt][3],h3,l3);
                __nv_bfloat162 t;
                t.x=h0; t.y=h1; *(__nv_bfloat162*)(CH + (size_t)rg * 512 + cg)       = t;
                t.x=l0; t.y=l1; *(__nv_bfloat162*)(CL + (size_t)rg * 512 + cg)       = t;
                t.x=h2; t.y=h3; *(__nv_bfloat162*)(CH + (size_t)(rg + 8) * 512 + cg) = t;
                t.x=l2; t.y=l3; *(__nv_bfloat162*)(CL + (size_t)(rg + 8) * 512 + cg) = t;
            }
        }
    } else {
        #pragma unroll
        for (int mt = 0; mt < 4; mt++) {
            int rg = row0 + wm + mt * 16 + (lane >> 2);
            #pragma unroll
            for (int nt = 0; nt < 4; nt++) {
                int cg = n0 + wn + nt * 8 + 2 * (lane & 3);
                *(float2*)(outp + (size_t)rg * 512 + cg)       = make_float2(c[mt][nt][0], c[mt][nt][1]);
                *(float2*)(outp + (size_t)(rg + 8) * 512 + cg) = make_float2(c[mt][nt][2], c[mt][nt][3]);
            }
        }
    }
}

// ---------------- HMMA attention (double-buffered loads) ---------------------
// Per tile s (head=s>>6, b=s&63): C = Kv@Qv^T *0.125; P = softmax; Hd = P@Vv.
#define TK      18432       // 128 rows * 144B (72 bf16, padded)
#define S_STG   73728       // phase-1 stage: 4 matrices (KH,KL,QH,QL)
#define V_STG   36864       // phase-2 stage: 2 matrices (VH,VL)
#define CF_STR  132         // fp32 logits row stride (floats)
#define P_STR   136         // P row stride (bf16)
#define OFF_P   147456      // after the two phase-1 stages
#define P_BYTES 34816       // 128 * 136 * 2
#define ATTN_SMEM 217088    // OFF_P + 2*P_BYTES

__global__ __launch_bounds__(256, 1) void attn_hmma()
{
    extern __shared__ char smc[];
    const uint32_t sb = s2u(smc);
    float* Cf = (float*)smc;                       // overlays phase-1 stage 0

    const int s = blockIdx.x;
    const int head = s >> 6;
    const int b = s & 63;
    const size_t tbase = ((size_t)b * 1024) * 512 + head * 64;

    const int tid  = threadIdx.x;
    const int lane = tid & 31;
    const int wid  = tid >> 5;
    const int a_row = lane & 15, a_hk = (lane >> 4) * 16;
    const int b_row = lane & 7,  b_hk = ((lane >> 3) & 1) * 16;

    auto loadKQ = [&](int kc, int st) {
        const size_t off = tbase + (size_t)kc * 512;
        const __nv_bfloat16* srcs[4] = { g_KH + off, g_KL + off, g_QH + off, g_QL + off };
        uint32_t base = sb + st * S_STG;
        #pragma unroll
        for (int it = 0; it < 16; it++) {
            int g = it * 256 + tid;
            int mat = g >> 10;
            int rem = g & 1023;
            int r = rem >> 3, j = rem & 7;
            cp16(base + mat * TK + r * 144 + j * 16, srcs[mat] + (size_t)r * 4096 + j * 8);
        }
    };
    auto loadV = [&](int cc, int st) {
        const size_t voff = tbase + (size_t)cc * 512;
        const __nv_bfloat16* vsrc[2] = { g_VH + voff, g_VL + voff };
        uint32_t base = sb + st * V_STG;
        #pragma unroll
        for (int it = 0; it < 8; it++) {
            int g = it * 256 + tid;
            int mat = g >> 10;
            int rem = g & 1023;
            int r = rem >> 3, j = rem & 7;
            cp16(base + mat * TK + r * 144 + j * 16, vsrc[mat] + (size_t)r * 4096 + j * 8);
        }
    };

    // ================= phase 1: C = Kv @ Qv^T ============================
    const int wm = (wid >> 2) * 64;     // 2x4 warps, warp 64x32
    const int wn = (wid & 3) * 32;

    float c1[4][4][4];
    #pragma unroll
    for (int mt = 0; mt < 4; mt++)
        #pragma unroll
        for (int nt = 0; nt < 4; nt++)
            #pragma unroll
            for (int q = 0; q < 4; q++) c1[mt][nt][q] = 0.f;

    loadKQ(0, 0); cp_commit();

    for (int kc = 0; kc < 8; kc++) {
        if (kc < 7) { loadKQ(kc + 1, (kc + 1) & 1); cp_commit(); cp_wait<1>(); }
        else        { cp_wait<0>(); }
        __syncthreads();

        uint32_t stb = sb + (kc & 1) * S_STG;
        #pragma unroll
        for (int ks = 0; ks < 4; ks++) {
            uint32_t ah[4][4], al[4][4], bh[4][2], bl[4][2];
            uint32_t aH = stb + (wm + a_row) * 144 + ks * 32 + a_hk;
            uint32_t aL = aH + TK;
            uint32_t bH = stb + 2 * TK + (wn + b_row) * 144 + ks * 32 + b_hk;
            uint32_t bL = bH + TK;
            #pragma unroll
            for (int mt = 0; mt < 4; mt++)
                ldsm4(aH + mt * 16 * 144, ah[mt][0], ah[mt][1], ah[mt][2], ah[mt][3]);
            #pragma unroll
            for (int nt = 0; nt < 4; nt++)
                ldsm2(bH + nt * 8 * 144, bh[nt][0], bh[nt][1]);
            #pragma unroll
            for (int nt = 0; nt < 4; nt++)
                #pragma unroll
                for (int mt = 0; mt < 4; mt++)
                    mma16816(c1[mt][nt][0], c1[mt][nt][1], c1[mt][nt][2], c1[mt][nt][3],
                             ah[mt][0], ah[mt][1], ah[mt][2], ah[mt][3], bh[nt][0], bh[nt][1]);
            #pragma unroll
            for (int nt = 0; nt < 4; nt++)
                ldsm2(bL + nt * 8 * 144, bl[nt][0], bl[nt][1]);
            #pragma unroll
            for (int nt = 0; nt < 4; nt++)
                #pragma unroll
                for (int mt = 0; mt < 4; mt++)
                    mma16816(c1[mt][nt][0], c1[mt][nt][1], c1[mt][nt][2], c1[mt][nt][3],
                             ah[mt][0], ah[mt][1], ah[mt][2], ah[mt][3], bl[nt][0], bl[nt][1]);
            #pragma unroll
            for (int mt = 0; mt < 4; mt++)
                ldsm4(aL + mt * 16 * 144, al[mt][0], al[mt][1], al[mt][2], al[mt][3]);
            #pragma unroll
            for (int nt = 0; nt < 4; nt++)
                #pragma unroll
                for (int mt = 0; mt < 4; mt++)
                    mma16816(c1[mt][nt][0], c1[mt][nt][1], c1[mt][nt][2], c1[mt][nt][3],
                             al[mt][0], al[mt][1], al[mt][2], al[mt][3], bh[nt][0], bh[nt][1]);
        }
        __syncthreads();
    }

    // write scaled logits to smem (overlays stage 0; all compute done)
    const float norm = 0.125f;
    #pragma unroll
    for (int mt = 0; mt < 4; mt++) {
        int rg = wm + mt * 16 + (lane >> 2);
        #pragma unroll
        for (int nt = 0; nt < 4; nt++) {
            int cg = wn + nt * 8 + 2 * (lane & 3);
            *(float2*)(Cf + rg * CF_STR + cg) =
                make_float2(c1[mt][nt][0] * norm, c1[mt][nt][1] * norm);
            *(float2*)(Cf + (rg + 8) * CF_STR + cg) =
                make_float2(c1[mt][nt][2] * norm, c1[mt][nt][3] * norm);
        }
    }
    __syncthreads();

    // ================= softmax: 2 threads per row ========================
    {
        int row = tid >> 1, half = tid & 1;
        float* crow = Cf + row * CF_STR + half * 64;
        float m = -1e30f;
        #pragma unroll
        for (int j = 0; j < 16; j++) {
            float4 v = *(float4*)(crow + j * 4);
            m = fmaxf(m, fmaxf(fmaxf(v.x, v.y), fmaxf(v.z, v.w)));
        }
        m = fmaxf(m, __shfl_xor_sync(0xffffffffu, m, 1));
        float ssum = 0.f;
        #pragma unroll
        for (int j = 0; j < 16; j++) {
            float4 v = *(float4*)(crow + j * 4);
            v.x = __expf(v.x - m); v.y = __expf(v.y - m);
            v.z = __expf(v.z - m); v.w = __expf(v.w - m);
            ssum += (v.x + v.y) + (v.z + v.w);
            *(float4*)(crow + j * 4) = v;
        }
        ssum += __shfl_xor_sync(0xffffffffu, ssum, 1);
        float inv = 1.f / ssum;
        __nv_bfloat16* ph = (__nv_bfloat16*)(smc + OFF_P) + row * P_STR + half * 64;
        __nv_bfloat16* pl = ph + (P_BYTES / 2);
        #pragma unroll
        for (int j = 0; j < 16; j++) {
            float4 v = *(float4*)(crow + j * 4);
            __nv_bfloat16 h0,h1,h2,h3,l0,l1,l2,l3;
            split1(v.x * inv, h0, l0); split1(v.y * inv, h1, l1);
            split1(v.z * inv, h2, l2); split1(v.w * inv, h3, l3);
            __nv_bfloat162 t;
            t.x=h0; t.y=h1; *(__nv_bfloat162*)(ph + j * 4)     = t;
            t.x=h2; t.y=h3; *(__nv_bfloat162*)(ph + j * 4 + 2) = t;
            t.x=l0; t.y=l1; *(__nv_bfloat162*)(pl + j * 4)     = t;
            t.x=l2; t.y=l3; *(__nv_bfloat162*)(pl + j * 4 + 2) = t;
        }
    }
    __syncthreads();   // softmax done: Cf region free for V stages

    // ================= phase 2: Hd = P @ Vv ==============================
    const int wm2 = (wid >> 2) * 64;    // 2x4 warps, warp 64x16 per 64-col chunk
    const int wn2 = (wid & 3) * 16;
    const int v_row = lane & 15;

    loadV(0, 0); cp_commit();

    for (int cc = 0; cc < 8; cc++) {
        if (cc < 7) { loadV(cc + 1, (cc + 1) & 1); cp_commit(); cp_wait<1>(); }
        else        { cp_wait<0>(); }
        __syncthreads();

        uint32_t stb2 = sb + (cc & 1) * V_STG;
        float c2[4][2][4];
        #pragma unroll
        for (int mt = 0; mt < 4; mt++)
            #pragma unroll
            for (int nt = 0; nt < 2; nt++)
                #pragma unroll
                for (int q = 0; q < 4; q++) c2[mt][nt][q] = 0.f;

        #pragma unroll
        for (int ks = 0; ks < 8; ks++) {
            uint32_t ph[4][4], pl[4][4], vh[2][2], vl[2][2];
            uint32_t pH = sb + OFF_P + (wm2 + a_row) * 272 + ks * 32 + a_hk;
            uint32_t pL = pH + P_BYTES;
            uint32_t vH = stb2 + (ks * 16 + v_row) * 144 + wn2 * 2;
            uint32_t vL = vH + TK;
            #pragma unroll
            for (int mt = 0; mt < 4; mt++)
                ldsm4(pH + mt * 16 * 272, ph[mt][0], ph[mt][1], ph[mt][2], ph[mt][3]);
            #pragma unroll
            for (int nt = 0; nt < 2; nt++)
                ldsm2t(vH + nt * 16, vh[nt][0], vh[nt][1]);
            #pragma unroll
            for (int nt = 0; nt < 2; nt++)
                #pragma unroll
                for (int mt = 0; mt < 4; mt++)
                    mma16816(c2[mt][nt][0], c2[mt][nt][1], c2[mt][nt][2], c2[mt][nt][3],
                             ph[mt][0], ph[mt][1], ph[mt][2], ph[mt][3], vh[nt][0], vh[nt][1]);
            #pragma unroll
            for (int nt = 0; nt < 2; nt++)
                ldsm2t(vL + nt * 16, vl[nt][0], vl[nt][1]);
            #pragma unroll
            for (int nt = 0; nt < 2; nt++)
                #pragma unroll
                for (int mt = 0; mt < 4; mt++)
                    mma16816(c2[mt][nt][0], c2[mt][nt][1], c2[mt][nt][2], c2[mt][nt][3],
                             ph[mt][0], ph[mt][1], ph[mt][2], ph[mt][3], vl[nt][0], vl[nt][1]);
            #pragma unroll
            for (int mt = 0; mt < 4; mt++)
                ldsm4(pL + mt * 16 * 272, pl[mt][0], pl[mt][1], pl[mt][2], pl[mt][3]);
            #pragma unroll
            for (int nt = 0; nt < 2; nt++)
                #pragma unroll
                for (int mt = 0; mt < 4; mt++)
                    mma16816(c2[mt][nt][0], c2[mt][nt][1], c2[mt][nt][2], c2[mt][nt][3],
                             pl[mt][0], pl[mt][1], pl[mt][2], pl[mt][3], vh[nt][0], vh[nt][1]);
        }

        // store Hd bf16 split
        #pragma unroll
        for (int mt = 0; mt < 4; mt++) {
            int rg = wm2 + mt * 16 + (lane >> 2);
            #pragma unroll
            for (int nt = 0; nt < 2; nt++) {
                int cg = cc * 64 + wn2 + nt * 8 + 2 * (lane & 3);
                size_t base0 = ((size_t)s * 128 + rg) * 512 + cg;
                size_t base1 = base0 + 8 * 512;
                __nv_bfloat16 h0,h1,h2,h3,l0,l1,l2,l3;
                split1(c2[mt][nt][0],h0,l0); split1(c2[mt][nt][1],h1,l1);
                split1(c2[mt][nt][2],h2,l2); split1(c2[mt][nt][3],h3,l3);
                __nv_bfloat162 t;
                t.x=h0; t.y=h1; *(__nv_bfloat162*)(g_HdH + base0) = t;
                t.x=l0; t.y=l1; *(__nv_bfloat162*)(g_HdL + base0) = t;
                t.x=h2; t.y=h3; *(__nv_bfloat162*)(g_HdH + base1) = t;
                t.x=l2; t.y=l3; *(__nv_bfloat162*)(g_HdL + base1) = t;
            }
        }
        __syncthreads();
    }
}

// ---------------------------------------------------------------------------
extern "C" void kernel_launch(void* const* d_in, const int* in_sizes, int n_in,
                              void* d_out, int out_size)
{
    (void)in_sizes; (void)n_in; (void)out_size;
    const float* h    = (const float*)d_in[0];
    const float* hOpp = (const float*)d_in[1];
    const float* Wq   = (const float*)d_in[2];
    const float* Wk   = (const float*)d_in[3];
    const float* Wv   = (const float*)d_in[4];
    const float* Wout = (const float*)d_in[5];
    float* out = (float*)d_out;

    cudaFuncSetAttribute(gemm_hmma,
                         cudaFuncAttributeMaxDynamicSharedMemorySize, GEMM_SMEM);
    cudaFuncSetAttribute(attn_hmma,
                         cudaFuncAttributeMaxDynamicSharedMemorySize, ATTN_SMEM);

    split_x <<<dim3(16384, 2), 256>>>(h, hOpp);
    wsplit  <<<dim3(512, 3), 256>>>(Wq, Wk, Wv);
    wosplit <<<512, 512>>>(Wout);

    gemm_hmma<<<dim3(512, 4, 3), 256, GEMM_SMEM>>>(-1, nullptr);  // K, Q, V projections

    attn_hmma<<<512, 256, ATTN_SMEM>>>();

    gemm_hmma<<<dim3(512, 4, 1), 256, GEMM_SMEM>>>(3, out);       // out = Hd @ Wout
}